// round 10
// baseline (speedup 1.0000x reference)
#include <cuda_runtime.h>
#include <cuda_bf16.h>
#include <cstdint>

// Problem constants (fixed by setup_inputs)
#define T_TOK 2048
#define NEXP  8
#define HD    1024
#define ID    4096
#define NSLOT 4096
#define PADROWS (NSLOT + 256)

// ---------------- scratch (static device globals; no allocation) -----------
__device__ int   g_counts[NEXP];
__device__ int   g_base[NEXP];
__device__ int   g_slot_tok[NSLOT];
__device__ float g_slot_w[NSLOT];
__device__ int   g_token_slot[NSLOT];

// split-bf16 operand buffers
__device__ __align__(256) __nv_bfloat16 g_w13h[(size_t)NEXP * 2 * ID * HD]; // [e][n=8192][k=1024]
__device__ __align__(256) __nv_bfloat16 g_w13l[(size_t)NEXP * 2 * ID * HD];
__device__ __align__(256) __nv_bfloat16 g_w2h [(size_t)NEXP * HD * ID];     // [e][n=1024][k=4096]
__device__ __align__(256) __nv_bfloat16 g_w2l [(size_t)NEXP * HD * ID];
__device__ __align__(256) __nv_bfloat16 g_xah [(size_t)PADROWS * HD];       // gathered x per slot
__device__ __align__(256) __nv_bfloat16 g_xal [(size_t)PADROWS * HD];
__device__ __align__(256) __nv_bfloat16 g_acth[(size_t)PADROWS * ID];
__device__ __align__(256) __nv_bfloat16 g_actl[(size_t)PADROWS * ID];

__device__ __align__(256) float g_h[(size_t)NSLOT * 2 * ID];    // gemm1 out fp32
__device__ __align__(256) float g_outslot[(size_t)NSLOT * HD];  // gemm2 out fp32

// ---------------- helpers ---------------------------------------------------
__device__ __forceinline__ uint32_t smem_u32(const void* p) {
    uint32_t a;
    asm("{ .reg .u64 t; cvta.to.shared.u64 t, %1; cvt.u32.u64 %0, t; }"
        : "=r"(a) : "l"(p));
    return a;
}
__device__ __forceinline__ void ldsm4(uint32_t* r, uint32_t a) {
    asm volatile("ldmatrix.sync.aligned.m8n8.x4.shared.b16 {%0,%1,%2,%3}, [%4];"
                 : "=r"(r[0]), "=r"(r[1]), "=r"(r[2]), "=r"(r[3]) : "r"(a));
}
__device__ __forceinline__ void cpasync16(uint32_t saddr, const void* gaddr) {
    asm volatile("cp.async.cg.shared.global [%0], [%1], 16;"
                 :: "r"(saddr), "l"(gaddr) : "memory");
}
#define CP_COMMIT() asm volatile("cp.async.commit_group;" ::: "memory")
#define CP_WAIT0()  asm volatile("cp.async.wait_group 0;" ::: "memory")

__device__ __forceinline__ void mma16816(float* d, const uint32_t* a,
                                         uint32_t b0, uint32_t b1) {
    asm volatile(
        "mma.sync.aligned.m16n8k16.row.col.f32.bf16.bf16.f32 "
        "{%0,%1,%2,%3}, {%4,%5,%6,%7}, {%8,%9}, {%0,%1,%2,%3};"
        : "+f"(d[0]), "+f"(d[1]), "+f"(d[2]), "+f"(d[3])
        : "r"(a[0]), "r"(a[1]), "r"(a[2]), "r"(a[3]), "r"(b0), "r"(b1));
}
__device__ __forceinline__ void split2(float v, __nv_bfloat16& h, __nv_bfloat16& l) {
    h = __float2bfloat16(v);
    l = __float2bfloat16(v - __bfloat162float(h));
}

// ---------------- routing: top2 + count + scan + assign, one block ----------
__global__ void k_route(const float* __restrict__ logits) {
    __shared__ int   csh[NEXP];
    __shared__ int   cur[NEXP];
    __shared__ int   te[NSLOT];
    __shared__ float tw[NSLOT];
    const int tid = threadIdx.x;
    if (tid < NEXP) csh[tid] = 0;
    __syncthreads();
    for (int t = tid; t < T_TOK; t += 256) {
        float l[NEXP];
#pragma unroll
        for (int e = 0; e < NEXP; e++) l[e] = logits[t * NEXP + e];
        int i1 = 0; float m1 = l[0];
        int i2 = -1; float m2 = -3.0e38f;
#pragma unroll
        for (int e = 1; e < NEXP; e++) {
            if (l[e] > m1) { m2 = m1; i2 = i1; m1 = l[e]; i1 = e; }
            else if (l[e] > m2) { m2 = l[e]; i2 = e; }
        }
        float r  = expf(m2 - m1);
        float w1 = 1.0f / (1.0f + r);
        float w2 = r * w1;
        te[t * 2 + 0] = i1;  te[t * 2 + 1] = i2;
        tw[t * 2 + 0] = w1;  tw[t * 2 + 1] = w2;
        atomicAdd(&csh[i1], 1);
        atomicAdd(&csh[i2], 1);
    }
    __syncthreads();
    if (tid == 0) {
        int acc = 0;
        for (int e = 0; e < NEXP; e++) {
            g_counts[e] = csh[e];
            g_base[e]   = acc;
            cur[e]      = acc;
            acc += csh[e];
        }
    }
    __syncthreads();
    for (int t = tid; t < T_TOK; t += 256) {
#pragma unroll
        for (int j = 0; j < 2; j++) {
            int e   = te[t * 2 + j];
            int pos = atomicAdd(&cur[e], 1);
            g_slot_tok[pos]         = t;
            g_slot_w[pos]           = tw[t * 2 + j];
            g_token_slot[t * 2 + j] = pos;
        }
    }
}

// ---------------- prolog: dequant + hi/lo split (merged w13 + w2) ----------
#define W13_BLOCKS ((NEXP * 128 * 8192) / 256)   // 32768
#define W2_BLOCKS  ((NEXP * 512 * 1024) / 256)   // 16384

__global__ void k_split_w(const int* __restrict__ qw13, const float* __restrict__ sc13,
                          const int* __restrict__ gi13,
                          const int* __restrict__ qw2, const float* __restrict__ sc2,
                          const int* __restrict__ gi2) {
    if (blockIdx.x < W13_BLOCKS) {
        int id = blockIdx.x * 256 + threadIdx.x;   // e(3) | n(13) | kp(7)
        int kp = id & 127;
        int n  = (id >> 7) & 8191;
        int e  = id >> 20;
        int q = qw13[((size_t)e * 128 + kp) * 8192 + n];
        const int*   g  = gi13 + e * HD + kp * 8;
        const float* sb = sc13 + (size_t)e * 8 * 8192 + n;
        alignas(16) __nv_bfloat16 h[8], l[8];
#pragma unroll
        for (int j = 0; j < 8; j++) {
            float v = (float)(((q >> (4 * j)) & 15) - 8) * sb[(size_t)g[j] * 8192];
            split2(v, h[j], l[j]);
        }
        size_t o = ((size_t)e * 8192 + n) * 1024 + kp * 8;
        *(uint4*)(g_w13h + o) = *(uint4*)h;
        *(uint4*)(g_w13l + o) = *(uint4*)l;
    } else {
        int id = (blockIdx.x - W13_BLOCKS) * 256 + threadIdx.x; // e(3)|n(10)|kp(9)
        int kp = id & 511;
        int n  = (id >> 9) & 1023;
        int e  = id >> 19;
        int q = qw2[((size_t)e * 512 + kp) * 1024 + n];
        const int*   g  = gi2 + e * ID + kp * 8;
        const float* sb = sc2 + (size_t)e * 32 * 1024 + n;
        alignas(16) __nv_bfloat16 h[8], l[8];
#pragma unroll
        for (int j = 0; j < 8; j++) {
            float v = (float)(((q >> (4 * j)) & 15) - 8) * sb[(size_t)g[j] * 1024];
            split2(v, h[j], l[j]);
        }
        size_t o = ((size_t)e * 1024 + n) * 4096 + kp * 8;
        *(uint4*)(g_w2h + o) = *(uint4*)h;
        *(uint4*)(g_w2l + o) = *(uint4*)l;
    }
}

// ---------------- prolog: gather x, split to hi/lo --------------------------
__global__ void k_split_x(const float* __restrict__ x) {
    int id = blockIdx.x * 256 + threadIdx.x;   // slot(12) | ko(7)
    int ko = id & 127;
    int s  = id >> 7;
    int tok = g_slot_tok[s];
    const float* xp = x + (size_t)tok * HD + ko * 8;
    float v[8];
    *(float4*)(v)     = *(const float4*)(xp);
    *(float4*)(v + 4) = *(const float4*)(xp + 4);
    alignas(16) __nv_bfloat16 h[8], l[8];
#pragma unroll
    for (int j = 0; j < 8; j++) split2(v[j], h[j], l[j]);
    size_t o = (size_t)s * HD + ko * 8;
    *(uint4*)(g_xah + o) = *(uint4*)h;
    *(uint4*)(g_xal + o) = *(uint4*)l;
}

// ---------------- activation: act = silu(gate)*up, split to hi/lo ----------
__global__ void k_act() {
    int id = blockIdx.x * 256 + threadIdx.x;   // slot(12) | io(9)
    int io = id & 511;
    int s  = id >> 9;
    const float* gp = g_h + (size_t)s * (2 * ID) + io * 8;
    float gv[8], uv[8];
    *(float4*)(gv)     = *(const float4*)(gp);
    *(float4*)(gv + 4) = *(const float4*)(gp + 4);
    *(float4*)(uv)     = *(const float4*)(gp + ID);
    *(float4*)(uv + 4) = *(const float4*)(gp + ID + 4);
    alignas(16) __nv_bfloat16 h[8], l[8];
#pragma unroll
    for (int j = 0; j < 8; j++) {
        float a = gv[j] / (1.0f + expf(-gv[j])) * uv[j];
        split2(a, h[j], l[j]);
    }
    size_t o = (size_t)s * ID + io * 8;
    *(uint4*)(g_acth + o) = *(uint4*)h;
    *(uint4*)(g_actl + o) = *(uint4*)l;
}

// ---------------- HMMA split-bf16 GEMM (mma.sync m16n8k16) -----------------
// Block 128x128, BK=64, 512 threads / 16 warps (32x32 warp tiles, 4x4 grid),
// 2-stage cp.async pipeline, issue-before-compute.
// SMEM per stage: 4 matrices [Ah, Al, Bh, Bl], each 128 rows x 64 bf16 with
// 144-byte row pitch (conflict-free ldmatrix: rows hit banks 4r mod 32).
// A and B fragments both via ldmatrix.x4 (non-trans: [row][k] layout == mma
// fragment mapping for both operands).
#define PITCH_B     144
#define MAT_BYTES   (128 * PITCH_B)     // 18432
#define STAGE_BYTES (4 * MAT_BYTES)     // 73728
#define SMEM_DYN    (2 * STAGE_BYTES)   // 147456
#define GTHREADS    512

template<int KTOT, bool G2>
__global__ __launch_bounds__(GTHREADS, 1) void k_gemm() {
    extern __shared__ __align__(128) char smem[];
    const int e   = blockIdx.z;
    const int cnt = g_counts[e];
    const int m0  = blockIdx.x * 128;
    if (m0 >= cnt) return;
    const int base = g_base[e];
    const int n0   = blockIdx.y * 128;
    const int tid  = threadIdx.x;
    const int lid  = tid & 31;
    const int wid  = tid >> 5;
    const int wm   = (wid >> 2) * 32;   // warp m offset: 0..96
    const int wn   = (wid & 3) * 32;    // warp n offset: 0..96

    const __nv_bfloat16 *Ah, *Al, *Bh, *Bl;
    if constexpr (G2) {
        Ah = g_acth; Al = g_actl;
        Bh = g_w2h + (size_t)e * HD * ID;
        Bl = g_w2l + (size_t)e * HD * ID;
    } else {
        Ah = g_xah; Al = g_xal;
        Bh = g_w13h + (size_t)e * 2 * ID * HD;
        Bl = g_w13l + (size_t)e * 2 * ID * HD;
    }

    const uint32_t sbase = smem_u32(smem);

    const __nv_bfloat16* mats[4] = {
        Ah + (size_t)(base + m0) * KTOT, Al + (size_t)(base + m0) * KTOT,
        Bh + (size_t)n0 * KTOT,          Bl + (size_t)n0 * KTOT };

    float acc[2][4][4];
#pragma unroll
    for (int i = 0; i < 2; i++)
#pragma unroll
        for (int j = 0; j < 4; j++)
#pragma unroll
            for (int k = 0; k < 4; k++) acc[i][j][k] = 0.0f;

    // ldmatrix lane addressing
    // A (x4: rows m0..m15, two k-halves): row = lid&15, khalf = lid>>4
    const uint32_t a_row  = (uint32_t)(lid & 15);
    const uint32_t a_koff = (uint32_t)((lid >> 4) * 16);
    // B (x4: {n-sub, k-half} x2x2): sel = lid>>3: nsub = sel>>1, khalf = sel&1
    const uint32_t b_row  = (uint32_t)(((lid >> 4) & 1) * 8 + (lid & 7));
    const uint32_t b_koff = (uint32_t)(((lid >> 3) & 1) * 16);

    constexpr int NCH = KTOT / 64;

    // issue stage 0 (4096 16B chunks, 8 per thread)
    {
#pragma unroll
        for (int it = 0; it < 8; it++) {
            int j   = it * GTHREADS + tid;
            int mat = j >> 10;
            int r   = (j >> 3) & 127;
            int c   = j & 7;
            cpasync16(sbase + (uint32_t)(mat * MAT_BYTES + r * PITCH_B + c * 16),
                      mats[mat] + (size_t)r * KTOT + c * 8);
        }
        CP_COMMIT();
    }

    for (int ch = 0; ch < NCH; ch++) {
        CP_WAIT0();
        __syncthreads();
        const uint32_t buf = sbase + (uint32_t)((ch & 1) * STAGE_BYTES);

        // issue next stage first so the copy overlaps this chunk's MMAs
        if (ch + 1 < NCH) {
            const uint32_t nb = sbase + (uint32_t)(((ch + 1) & 1) * STAGE_BYTES);
            const int k0 = (ch + 1) * 64;
#pragma unroll
            for (int it = 0; it < 8; it++) {
                int j   = it * GTHREADS + tid;
                int mat = j >> 10;
                int r   = (j >> 3) & 127;
                int c   = j & 7;
                cpasync16(nb + (uint32_t)(mat * MAT_BYTES + r * PITCH_B + c * 16),
                          mats[mat] + (size_t)r * KTOT + k0 + c * 8);
            }
            CP_COMMIT();
        }

#pragma unroll
        for (int s = 0; s < 4; s++) {
            // A fragments: mi x {hi,lo}
            uint32_t ah[2][4], al[2][4];
#pragma unroll
            for (int mi = 0; mi < 2; mi++) {
                uint32_t ra = buf + (uint32_t)((wm + mi * 16 + a_row) * PITCH_B)
                                  + (uint32_t)(s * 32) + a_koff;
                ldsm4(ah[mi], ra);
                ldsm4(al[mi], ra + MAT_BYTES);
            }
            // B fragments: ni-pair x {hi,lo}; x4 = {b0,b1} for 2 n-tiles
            uint32_t bh[2][4], bl[2][4];
#pragma unroll
            for (int p = 0; p < 2; p++) {
                uint32_t rb = buf + 2u * MAT_BYTES
                                  + (uint32_t)((wn + p * 16 + b_row) * PITCH_B)
                                  + (uint32_t)(s * 32) + b_koff;
                ldsm4(bh[p], rb);
                ldsm4(bl[p], rb + MAT_BYTES);
            }
#pragma unroll
            for (int ni = 0; ni < 4; ni++) {
                uint32_t bh0 = bh[ni >> 1][(ni & 1) * 2];
                uint32_t bh1 = bh[ni >> 1][(ni & 1) * 2 + 1];
                uint32_t bl0 = bl[ni >> 1][(ni & 1) * 2];
                uint32_t bl1 = bl[ni >> 1][(ni & 1) * 2 + 1];
#pragma unroll
                for (int mi = 0; mi < 2; mi++) {
                    mma16816(acc[mi][ni], ah[mi], bh0, bh1);
                    mma16816(acc[mi][ni], ah[mi], bl0, bl1);
                    mma16816(acc[mi][ni], al[mi], bh0, bh1);
                }
            }
        }
    }

    // epilogue: D fragment -> global fp32
    const int lr = lid >> 2;
    const int lc = (lid & 3) * 2;
#pragma unroll
    for (int mi = 0; mi < 2; mi++) {
#pragma unroll
        for (int half = 0; half < 2; half++) {
            int row = m0 + wm + mi * 16 + half * 8 + lr;   // expert-local m
            if (row < cnt) {
                int gs = base + row;
                if constexpr (!G2) {
                    float* dst = g_h + (size_t)gs * (2 * ID) + n0 + wn + lc;
#pragma unroll
                    for (int ni = 0; ni < 4; ni++) {
                        float2 v = make_float2(acc[mi][ni][half * 2],
                                               acc[mi][ni][half * 2 + 1]);
                        *(float2*)(dst + ni * 8) = v;
                    }
                } else {
                    float w = g_slot_w[gs];
                    float* dst = g_outslot + (size_t)gs * HD + n0 + wn + lc;
#pragma unroll
                    for (int ni = 0; ni < 4; ni++) {
                        float2 v = make_float2(acc[mi][ni][half * 2] * w,
                                               acc[mi][ni][half * 2 + 1] * w);
                        *(float2*)(dst + ni * 8) = v;
                    }
                }
            }
        }
    }
}

// ---------------- combine: out[t] = outslot[s0] + outslot[s1] --------------
__global__ void k_combine(float* __restrict__ out) {
    int t = blockIdx.y;
    int n = blockIdx.x * 256 + threadIdx.x;
    int s0 = g_token_slot[t * 2 + 0];
    int s1 = g_token_slot[t * 2 + 1];
    out[(size_t)t * HD + n] = g_outslot[(size_t)s0 * HD + n] +
                              g_outslot[(size_t)s1 * HD + n];
}

// ---------------- launch ----------------------------------------------------
extern "C" void kernel_launch(void* const* d_in, const int* in_sizes, int n_in,
                              void* d_out, int out_size) {
    const float* x      = (const float*)d_in[0];
    const float* logits = (const float*)d_in[1];
    const int*   w13_q  = (const int*)  d_in[2];
    const int*   w2_q   = (const int*)  d_in[3];
    const float* w13_s  = (const float*)d_in[4];
    const float* w2_s   = (const float*)d_in[5];
    const int*   w13_g  = (const int*)  d_in[6];
    const int*   w2_g   = (const int*)  d_in[7];
    float* out = (float*)d_out;
    (void)in_sizes; (void)n_in; (void)out_size;

    static int s_attr_done = 0;
    if (!s_attr_done) {
        cudaFuncSetAttribute(k_gemm<HD, false>,
                             cudaFuncAttributeMaxDynamicSharedMemorySize, SMEM_DYN);
        cudaFuncSetAttribute(k_gemm<ID, true>,
                             cudaFuncAttributeMaxDynamicSharedMemorySize, SMEM_DYN);
        s_attr_done = 1;
    }

    // launch order: gemm1 is our launch index 3 -> the one ncu captures
    k_route<<<1, 256>>>(logits);                               // 0
    k_split_w<<<W13_BLOCKS + W2_BLOCKS, 256>>>(w13_q, w13_s, w13_g,
                                               w2_q, w2_s, w2_g); // 1
    k_split_x<<<(NSLOT * (HD / 8)) / 256, 256>>>(x);           // 2

    // GEMM1: h = xa @ W13^T  (x = m-tiles, y = 64 n-tiles, z = experts)
    k_gemm<HD, false><<<dim3(NSLOT / 128, 2 * ID / 128, NEXP), GTHREADS, SMEM_DYN>>>(); // 3

    k_act<<<(NSLOT * (ID / 8)) / 256, 256>>>();                // 4

    // GEMM2: outslot = act @ W2^T  (y = 8 n-tiles)
    k_gemm<ID, true><<<dim3(NSLOT / 128, HD / 128, NEXP), GTHREADS, SMEM_DYN>>>(); // 5

    k_combine<<<dim3(HD / 256, T_TOK), 256>>>(out);            // 6
}

// round 11
// speedup vs baseline: 1.1215x; 1.1215x over previous
#include <cuda_runtime.h>
#include <cuda_bf16.h>
#include <cstdint>

// Problem constants (fixed by setup_inputs)
#define T_TOK 2048
#define NEXP  8
#define HD    1024
#define ID    4096
#define NSLOT 4096
#define PADROWS (NSLOT + 256)
#define NTILES  72              // max m-tiles of 64 over experts: 64 + 7 rounding

// ---------------- scratch (static device globals; no allocation) -----------
__device__ int   g_counts[NEXP];
__device__ int   g_base[NEXP];
__device__ int   g_slot_tok[NSLOT];
__device__ float g_slot_w[NSLOT];
__device__ int   g_token_slot[NSLOT];
__device__ int   g_tile_e[NTILES];
__device__ int   g_tile_m0[NTILES];

// split-bf16 operand buffers
__device__ __align__(256) __nv_bfloat16 g_w13h[(size_t)NEXP * 2 * ID * HD]; // [e][n=8192][k=1024]
__device__ __align__(256) __nv_bfloat16 g_w13l[(size_t)NEXP * 2 * ID * HD];
__device__ __align__(256) __nv_bfloat16 g_w2h [(size_t)NEXP * HD * ID];     // [e][n=1024][k=4096]
__device__ __align__(256) __nv_bfloat16 g_w2l [(size_t)NEXP * HD * ID];
__device__ __align__(256) __nv_bfloat16 g_xah [(size_t)PADROWS * HD];       // gathered x per slot
__device__ __align__(256) __nv_bfloat16 g_xal [(size_t)PADROWS * HD];
__device__ __align__(256) __nv_bfloat16 g_acth[(size_t)PADROWS * ID];
__device__ __align__(256) __nv_bfloat16 g_actl[(size_t)PADROWS * ID];

__device__ __align__(256) float g_h[(size_t)NSLOT * 2 * ID];    // gemm1 out fp32
__device__ __align__(256) float g_outslot[(size_t)NSLOT * HD];  // gemm2 out fp32

// ---------------- helpers ---------------------------------------------------
__device__ __forceinline__ uint32_t smem_u32(const void* p) {
    uint32_t a;
    asm("{ .reg .u64 t; cvta.to.shared.u64 t, %1; cvt.u32.u64 %0, t; }"
        : "=r"(a) : "l"(p));
    return a;
}
__device__ __forceinline__ void ldsm4(uint32_t* r, uint32_t a) {
    asm volatile("ldmatrix.sync.aligned.m8n8.x4.shared.b16 {%0,%1,%2,%3}, [%4];"
                 : "=r"(r[0]), "=r"(r[1]), "=r"(r[2]), "=r"(r[3]) : "r"(a));
}
__device__ __forceinline__ void cpasync16(uint32_t saddr, const void* gaddr) {
    asm volatile("cp.async.cg.shared.global [%0], [%1], 16;"
                 :: "r"(saddr), "l"(gaddr) : "memory");
}
#define CP_COMMIT() asm volatile("cp.async.commit_group;" ::: "memory")
#define CP_WAIT0()  asm volatile("cp.async.wait_group 0;" ::: "memory")

__device__ __forceinline__ void mma16816(float* d, const uint32_t* a,
                                         uint32_t b0, uint32_t b1) {
    asm volatile(
        "mma.sync.aligned.m16n8k16.row.col.f32.bf16.bf16.f32 "
        "{%0,%1,%2,%3}, {%4,%5,%6,%7}, {%8,%9}, {%0,%1,%2,%3};"
        : "+f"(d[0]), "+f"(d[1]), "+f"(d[2]), "+f"(d[3])
        : "r"(a[0]), "r"(a[1]), "r"(a[2]), "r"(a[3]), "r"(b0), "r"(b1));
}
__device__ __forceinline__ void split2(float v, __nv_bfloat16& h, __nv_bfloat16& l) {
    h = __float2bfloat16(v);
    l = __float2bfloat16(v - __bfloat162float(h));
}

// ---------------- routing: top2 + count + scan + assign + tile table --------
__global__ void k_route(const float* __restrict__ logits) {
    __shared__ int   csh[NEXP];
    __shared__ int   cur[NEXP];
    __shared__ int   te[NSLOT];
    __shared__ float tw[NSLOT];
    const int tid = threadIdx.x;
    if (tid < NEXP) csh[tid] = 0;
    __syncthreads();
    for (int t = tid; t < T_TOK; t += 256) {
        float l[NEXP];
#pragma unroll
        for (int e = 0; e < NEXP; e++) l[e] = logits[t * NEXP + e];
        int i1 = 0; float m1 = l[0];
        int i2 = -1; float m2 = -3.0e38f;
#pragma unroll
        for (int e = 1; e < NEXP; e++) {
            if (l[e] > m1) { m2 = m1; i2 = i1; m1 = l[e]; i1 = e; }
            else if (l[e] > m2) { m2 = l[e]; i2 = e; }
        }
        float r  = expf(m2 - m1);
        float w1 = 1.0f / (1.0f + r);
        float w2 = r * w1;
        te[t * 2 + 0] = i1;  te[t * 2 + 1] = i2;
        tw[t * 2 + 0] = w1;  tw[t * 2 + 1] = w2;
        atomicAdd(&csh[i1], 1);
        atomicAdd(&csh[i2], 1);
    }
    __syncthreads();
    if (tid == 0) {
        int acc = 0;
        for (int e = 0; e < NEXP; e++) {
            g_counts[e] = csh[e];
            g_base[e]   = acc;
            cur[e]      = acc;
            acc += csh[e];
        }
        // tile table: 64-row m-tiles per expert
        int nt = 0;
        for (int e = 0; e < NEXP; e++)
            for (int m0 = 0; m0 < csh[e]; m0 += 64) {
                g_tile_e[nt]  = e;
                g_tile_m0[nt] = m0;
                nt++;
            }
        for (; nt < NTILES; nt++) g_tile_e[nt] = -1;
    }
    __syncthreads();
    for (int t = tid; t < T_TOK; t += 256) {
#pragma unroll
        for (int j = 0; j < 2; j++) {
            int e   = te[t * 2 + j];
            int pos = atomicAdd(&cur[e], 1);
            g_slot_tok[pos]         = t;
            g_slot_w[pos]           = tw[t * 2 + j];
            g_token_slot[t * 2 + j] = pos;
        }
    }
}

// ---------------- prolog: dequant + hi/lo split (merged w13 + w2) ----------
#define W13_BLOCKS ((NEXP * 128 * 8192) / 256)   // 32768
#define W2_BLOCKS  ((NEXP * 512 * 1024) / 256)   // 16384

__global__ void k_split_w(const int* __restrict__ qw13, const float* __restrict__ sc13,
                          const int* __restrict__ gi13,
                          const int* __restrict__ qw2, const float* __restrict__ sc2,
                          const int* __restrict__ gi2) {
    if (blockIdx.x < W13_BLOCKS) {
        int id = blockIdx.x * 256 + threadIdx.x;   // e(3) | n(13) | kp(7)
        int kp = id & 127;
        int n  = (id >> 7) & 8191;
        int e  = id >> 20;
        int q = qw13[((size_t)e * 128 + kp) * 8192 + n];
        const int*   g  = gi13 + e * HD + kp * 8;
        const float* sb = sc13 + (size_t)e * 8 * 8192 + n;
        alignas(16) __nv_bfloat16 h[8], l[8];
#pragma unroll
        for (int j = 0; j < 8; j++) {
            float v = (float)(((q >> (4 * j)) & 15) - 8) * sb[(size_t)g[j] * 8192];
            split2(v, h[j], l[j]);
        }
        size_t o = ((size_t)e * 8192 + n) * 1024 + kp * 8;
        *(uint4*)(g_w13h + o) = *(uint4*)h;
        *(uint4*)(g_w13l + o) = *(uint4*)l;
    } else {
        int id = (blockIdx.x - W13_BLOCKS) * 256 + threadIdx.x; // e(3)|n(10)|kp(9)
        int kp = id & 511;
        int n  = (id >> 9) & 1023;
        int e  = id >> 19;
        int q = qw2[((size_t)e * 512 + kp) * 1024 + n];
        const int*   g  = gi2 + e * ID + kp * 8;
        const float* sb = sc2 + (size_t)e * 32 * 1024 + n;
        alignas(16) __nv_bfloat16 h[8], l[8];
#pragma unroll
        for (int j = 0; j < 8; j++) {
            float v = (float)(((q >> (4 * j)) & 15) - 8) * sb[(size_t)g[j] * 1024];
            split2(v, h[j], l[j]);
        }
        size_t o = ((size_t)e * 1024 + n) * 4096 + kp * 8;
        *(uint4*)(g_w2h + o) = *(uint4*)h;
        *(uint4*)(g_w2l + o) = *(uint4*)l;
    }
}

// ---------------- prolog: gather x, split to hi/lo --------------------------
__global__ void k_split_x(const float* __restrict__ x) {
    int id = blockIdx.x * 256 + threadIdx.x;   // slot(12) | ko(7)
    int ko = id & 127;
    int s  = id >> 7;
    int tok = g_slot_tok[s];
    const float* xp = x + (size_t)tok * HD + ko * 8;
    float v[8];
    *(float4*)(v)     = *(const float4*)(xp);
    *(float4*)(v + 4) = *(const float4*)(xp + 4);
    alignas(16) __nv_bfloat16 h[8], l[8];
#pragma unroll
    for (int j = 0; j < 8; j++) split2(v[j], h[j], l[j]);
    size_t o = (size_t)s * HD + ko * 8;
    *(uint4*)(g_xah + o) = *(uint4*)h;
    *(uint4*)(g_xal + o) = *(uint4*)l;
}

// ---------------- activation: act = silu(gate)*up, split to hi/lo ----------
__global__ void k_act() {
    int id = blockIdx.x * 256 + threadIdx.x;   // slot(12) | io(9)
    int io = id & 511;
    int s  = id >> 9;
    const float* gp = g_h + (size_t)s * (2 * ID) + io * 8;
    float gv[8], uv[8];
    *(float4*)(gv)     = *(const float4*)(gp);
    *(float4*)(gv + 4) = *(const float4*)(gp + 4);
    *(float4*)(uv)     = *(const float4*)(gp + ID);
    *(float4*)(uv + 4) = *(const float4*)(gp + ID + 4);
    alignas(16) __nv_bfloat16 h[8], l[8];
#pragma unroll
    for (int j = 0; j < 8; j++) {
        float a = gv[j] / (1.0f + expf(-gv[j])) * uv[j];
        split2(a, h[j], l[j]);
    }
    size_t o = (size_t)s * ID + io * 8;
    *(uint4*)(g_acth + o) = *(uint4*)h;
    *(uint4*)(g_actl + o) = *(uint4*)l;
}

// ---------------- HMMA split-bf16 GEMM (mma.sync m16n8k16) -----------------
// Block 64x128, BK=64, 256 threads / 8 warps (32x32 warp tiles, 2x4 grid),
// 2-stage cp.async pipeline, issue-before-compute, 2 CTAs per SM
// (cross-CTA overlap fills wait/barrier bubbles in the tensor pipe).
// SMEM per stage: Ah, Al (64 rows) + Bh, Bl (128 rows), 144-byte row pitch.
#define PITCH_B 144
#define AMAT    (64 * PITCH_B)               // 9216
#define BMAT    (128 * PITCH_B)              // 18432
#define STAGE_BYTES (2 * AMAT + 2 * BMAT)    // 55296
#define SMEM_DYN    (2 * STAGE_BYTES)        // 110592
#define GTHREADS    256

template<int KTOT, bool G2>
__global__ __launch_bounds__(GTHREADS, 2) void k_gemm() {
    extern __shared__ __align__(128) char smem[];
    const int e = g_tile_e[blockIdx.x];
    if (e < 0) return;
    const int m0   = g_tile_m0[blockIdx.x];
    const int cnt  = g_counts[e];
    const int base = g_base[e];
    const int n0   = blockIdx.y * 128;
    const int tid  = threadIdx.x;
    const int lid  = tid & 31;
    const int wid  = tid >> 5;
    const int wm   = (wid >> 2) * 32;   // warp m offset: 0 / 32
    const int wn   = (wid & 3) * 32;    // warp n offset: 0..96

    const __nv_bfloat16 *Ah, *Al, *Bh, *Bl;
    if constexpr (G2) {
        Ah = g_acth; Al = g_actl;
        Bh = g_w2h + (size_t)e * HD * ID;
        Bl = g_w2l + (size_t)e * HD * ID;
    } else {
        Ah = g_xah; Al = g_xal;
        Bh = g_w13h + (size_t)e * 2 * ID * HD;
        Bl = g_w13l + (size_t)e * 2 * ID * HD;
    }

    const uint32_t sbase = smem_u32(smem);

    const __nv_bfloat16* Amats[2] = {
        Ah + (size_t)(base + m0) * KTOT, Al + (size_t)(base + m0) * KTOT };
    const __nv_bfloat16* Bmats[2] = {
        Bh + (size_t)n0 * KTOT,          Bl + (size_t)n0 * KTOT };

    float acc[2][4][4];
#pragma unroll
    for (int i = 0; i < 2; i++)
#pragma unroll
        for (int j = 0; j < 4; j++)
#pragma unroll
            for (int k = 0; k < 4; k++) acc[i][j][k] = 0.0f;

    // ldmatrix lane addressing
    const uint32_t a_row  = (uint32_t)(lid & 15);
    const uint32_t a_koff = (uint32_t)((lid >> 4) * 16);
    const uint32_t b_row  = (uint32_t)(((lid >> 4) & 1) * 8 + (lid & 7));
    const uint32_t b_koff = (uint32_t)(((lid >> 3) & 1) * 16);

    constexpr int NCH = KTOT / 64;

    // stage fill: 3072 16B chunks (A: 2x64x8 = 1024, B: 2x128x8 = 2048)
    auto issue_stage = [&](uint32_t sb, int k0) {
#pragma unroll
        for (int it = 0; it < 12; it++) {
            int j = it * GTHREADS + tid;
            const __nv_bfloat16* src;
            uint32_t dst;
            if (j < 1024) {
                int mat = j >> 9, jj = j & 511;
                int r = jj >> 3, c = jj & 7;
                src = Amats[mat] + (size_t)r * KTOT + k0 + c * 8;
                dst = (uint32_t)(mat * AMAT + r * PITCH_B + c * 16);
            } else {
                int jb = j - 1024;
                int mat = jb >> 10, jj = jb & 1023;
                int r = jj >> 3, c = jj & 7;
                src = Bmats[mat] + (size_t)r * KTOT + k0 + c * 8;
                dst = (uint32_t)(2 * AMAT + mat * BMAT + r * PITCH_B + c * 16);
            }
            cpasync16(sb + dst, src);
        }
        CP_COMMIT();
    };

    issue_stage(sbase, 0);

    for (int ch = 0; ch < NCH; ch++) {
        CP_WAIT0();
        __syncthreads();
        const uint32_t buf = sbase + (uint32_t)((ch & 1) * STAGE_BYTES);

        // issue next stage first so the copy overlaps this chunk's MMAs
        if (ch + 1 < NCH)
            issue_stage(sbase + (uint32_t)(((ch + 1) & 1) * STAGE_BYTES),
                        (ch + 1) * 64);

#pragma unroll
        for (int s = 0; s < 4; s++) {
            uint32_t ah[2][4], al[2][4];
#pragma unroll
            for (int mi = 0; mi < 2; mi++) {
                uint32_t ra = buf + (uint32_t)((wm + mi * 16 + a_row) * PITCH_B)
                                  + (uint32_t)(s * 32) + a_koff;
                ldsm4(ah[mi], ra);
                ldsm4(al[mi], ra + AMAT);
            }
            uint32_t bh[2][4], bl[2][4];
#pragma unroll
            for (int p = 0; p < 2; p++) {
                uint32_t rb = buf + 2u * AMAT
                                  + (uint32_t)((wn + p * 16 + b_row) * PITCH_B)
                                  + (uint32_t)(s * 32) + b_koff;
                ldsm4(bh[p], rb);
                ldsm4(bl[p], rb + BMAT);
            }
#pragma unroll
            for (int ni = 0; ni < 4; ni++) {
                uint32_t bh0 = bh[ni >> 1][(ni & 1) * 2];
                uint32_t bh1 = bh[ni >> 1][(ni & 1) * 2 + 1];
                uint32_t bl0 = bl[ni >> 1][(ni & 1) * 2];
                uint32_t bl1 = bl[ni >> 1][(ni & 1) * 2 + 1];
#pragma unroll
                for (int mi = 0; mi < 2; mi++) {
                    mma16816(acc[mi][ni], ah[mi], bh0, bh1);
                    mma16816(acc[mi][ni], ah[mi], bl0, bl1);
                    mma16816(acc[mi][ni], al[mi], bh0, bh1);
                }
            }
        }
    }

    // epilogue: D fragment -> global fp32
    const int lr = lid >> 2;
    const int lc = (lid & 3) * 2;
#pragma unroll
    for (int mi = 0; mi < 2; mi++) {
#pragma unroll
        for (int half = 0; half < 2; half++) {
            int row = m0 + wm + mi * 16 + half * 8 + lr;   // expert-local m
            if (row < cnt) {
                int gs = base + row;
                if constexpr (!G2) {
                    float* dst = g_h + (size_t)gs * (2 * ID) + n0 + wn + lc;
#pragma unroll
                    for (int ni = 0; ni < 4; ni++) {
                        float2 v = make_float2(acc[mi][ni][half * 2],
                                               acc[mi][ni][half * 2 + 1]);
                        *(float2*)(dst + ni * 8) = v;
                    }
                } else {
                    float w = g_slot_w[gs];
                    float* dst = g_outslot + (size_t)gs * HD + n0 + wn + lc;
#pragma unroll
                    for (int ni = 0; ni < 4; ni++) {
                        float2 v = make_float2(acc[mi][ni][half * 2] * w,
                                               acc[mi][ni][half * 2 + 1] * w);
                        *(float2*)(dst + ni * 8) = v;
                    }
                }
            }
        }
    }
}

// ---------------- combine: out[t] = outslot[s0] + outslot[s1] --------------
__global__ void k_combine(float* __restrict__ out) {
    int t = blockIdx.y;
    int n = blockIdx.x * 256 + threadIdx.x;
    int s0 = g_token_slot[t * 2 + 0];
    int s1 = g_token_slot[t * 2 + 1];
    out[(size_t)t * HD + n] = g_outslot[(size_t)s0 * HD + n] +
                              g_outslot[(size_t)s1 * HD + n];
}

// ---------------- launch ----------------------------------------------------
extern "C" void kernel_launch(void* const* d_in, const int* in_sizes, int n_in,
                              void* d_out, int out_size) {
    const float* x      = (const float*)d_in[0];
    const float* logits = (const float*)d_in[1];
    const int*   w13_q  = (const int*)  d_in[2];
    const int*   w2_q   = (const int*)  d_in[3];
    const float* w13_s  = (const float*)d_in[4];
    const float* w2_s   = (const float*)d_in[5];
    const int*   w13_g  = (const int*)  d_in[6];
    const int*   w2_g   = (const int*)  d_in[7];
    float* out = (float*)d_out;
    (void)in_sizes; (void)n_in; (void)out_size;

    static int s_attr_done = 0;
    if (!s_attr_done) {
        cudaFuncSetAttribute(k_gemm<HD, false>,
                             cudaFuncAttributeMaxDynamicSharedMemorySize, SMEM_DYN);
        cudaFuncSetAttribute(k_gemm<ID, true>,
                             cudaFuncAttributeMaxDynamicSharedMemorySize, SMEM_DYN);
        s_attr_done = 1;
    }

    // launch order: gemm1 is our launch index 3 -> the one ncu captures
    k_route<<<1, 256>>>(logits);                               // 0
    k_split_w<<<W13_BLOCKS + W2_BLOCKS, 256>>>(w13_q, w13_s, w13_g,
                                               w2_q, w2_s, w2_g); // 1
    k_split_x<<<(NSLOT * (HD / 8)) / 256, 256>>>(x);           // 2

    // GEMM1: h = xa @ W13^T  (x = m-tiles via table, y = 64 n-tiles)
    k_gemm<HD, false><<<dim3(NTILES, 2 * ID / 128), GTHREADS, SMEM_DYN>>>(); // 3

    k_act<<<(NSLOT * (ID / 8)) / 256, 256>>>();                // 4

    // GEMM2: outslot = act @ W2^T  (y = 8 n-tiles)
    k_gemm<ID, true><<<dim3(NTILES, HD / 128), GTHREADS, SMEM_DYN>>>(); // 5

    k_combine<<<dim3(HD / 256, T_TOK), 256>>>(out);            // 6
}

// round 12
// speedup vs baseline: 1.3459x; 1.2000x over previous
#include <cuda_runtime.h>
#include <cuda_bf16.h>
#include <cstdint>

// Problem constants (fixed by setup_inputs)
#define T_TOK 2048
#define NEXP  8
#define HD    1024
#define ID    4096
#define NSLOT 4096
#define PADROWS (NSLOT + 256)
#define NTILES  72              // max m-tiles of 64 over experts

// permuted-k geometry: groups padded to 16, totals padded to 64
#define K13P   1152             // >= 1024 + 8*15, mult of 64
#define K2P    4608             // >= 4096 + 32*15, mult of 64
#define SCHED13 72              // 16-step entries
#define SCHED2  288

// ---------------- scratch (static device globals; no allocation) -----------
__device__ int   g_counts[NEXP];
__device__ int   g_base[NEXP];
__device__ int   g_slot_tok[NSLOT];
__device__ int   g_slot_e[NSLOT];
__device__ float g_slot_w[NSLOT];
__device__ int   g_token_slot[NSLOT];
__device__ int   g_tile_e[NTILES];
__device__ int   g_tile_m0[NTILES];

__device__ int   g_perm13[NEXP * K13P];
__device__ int   g_perm2 [NEXP * K2P];
__device__ int   g_sched13[NEXP * SCHED13];   // gid | 0x100 flush flag
__device__ int   g_sched2 [NEXP * SCHED2];
__device__ int   g_nch13[NEXP];
__device__ int   g_nch2 [NEXP];

// exact-integer weights (bf16 of q-8), k-permuted, [e][n][k']
__device__ __align__(256) __nv_bfloat16 g_q13p[(size_t)NEXP * 2 * ID * K13P];
__device__ __align__(256) __nv_bfloat16 g_q2p [(size_t)NEXP * HD * K2P];
// hi/lo split activations, k-permuted per slot's expert
__device__ __align__(256) __nv_bfloat16 g_xah [(size_t)PADROWS * K13P];
__device__ __align__(256) __nv_bfloat16 g_xal [(size_t)PADROWS * K13P];
__device__ __align__(256) __nv_bfloat16 g_acth[(size_t)PADROWS * K2P];
__device__ __align__(256) __nv_bfloat16 g_actl[(size_t)PADROWS * K2P];

__device__ __align__(256) float g_h[(size_t)NSLOT * 2 * ID];    // gemm1 out fp32
__device__ __align__(256) float g_outslot[(size_t)NSLOT * HD];  // gemm2 out fp32

// ---------------- helpers ---------------------------------------------------
__device__ __forceinline__ uint32_t smem_u32(const void* p) {
    uint32_t a;
    asm("{ .reg .u64 t; cvta.to.shared.u64 t, %1; cvt.u32.u64 %0, t; }"
        : "=r"(a) : "l"(p));
    return a;
}
__device__ __forceinline__ void ldsm4(uint32_t* r, uint32_t a) {
    asm volatile("ldmatrix.sync.aligned.m8n8.x4.shared.b16 {%0,%1,%2,%3}, [%4];"
                 : "=r"(r[0]), "=r"(r[1]), "=r"(r[2]), "=r"(r[3]) : "r"(a));
}
__device__ __forceinline__ void cpasync16(uint32_t saddr, const void* gaddr) {
    asm volatile("cp.async.cg.shared.global [%0], [%1], 16;"
                 :: "r"(saddr), "l"(gaddr) : "memory");
}
#define CP_COMMIT() asm volatile("cp.async.commit_group;" ::: "memory")
#define CP_WAIT0()  asm volatile("cp.async.wait_group 0;" ::: "memory")

__device__ __forceinline__ void mma16816(float* d, const uint32_t* a,
                                         uint32_t b0, uint32_t b1) {
    asm volatile(
        "mma.sync.aligned.m16n8k16.row.col.f32.bf16.bf16.f32 "
        "{%0,%1,%2,%3}, {%4,%5,%6,%7}, {%8,%9}, {%0,%1,%2,%3};"
        : "+f"(d[0]), "+f"(d[1]), "+f"(d[2]), "+f"(d[3])
        : "r"(a[0]), "r"(a[1]), "r"(a[2]), "r"(a[3]), "r"(b0), "r"(b1));
}
__device__ __forceinline__ void split2(float v, __nv_bfloat16& h, __nv_bfloat16& l) {
    h = __float2bfloat16(v);
    l = __float2bfloat16(v - __bfloat162float(h));
}

// ---------------- routing + permutation build (grid = 17 blocks) -----------
// block 0: top2 routing + counts + scan + assign + tile table
// blocks 1..16: deterministic group-sort permutation + schedule for
//               (w13, w2) x expert
__global__ void k_route(const float* __restrict__ logits,
                        const int* __restrict__ gi13,
                        const int* __restrict__ gi2) {
    const int tid = threadIdx.x;
    if (blockIdx.x == 0) {
        __shared__ int   csh[NEXP];
        __shared__ int   cur[NEXP];
        __shared__ int   te[NSLOT];
        __shared__ float tw[NSLOT];
        if (tid < NEXP) csh[tid] = 0;
        __syncthreads();
        for (int t = tid; t < T_TOK; t += 256) {
            float l[NEXP];
#pragma unroll
            for (int e = 0; e < NEXP; e++) l[e] = logits[t * NEXP + e];
            int i1 = 0; float m1 = l[0];
            int i2 = -1; float m2 = -3.0e38f;
#pragma unroll
            for (int e = 1; e < NEXP; e++) {
                if (l[e] > m1) { m2 = m1; i2 = i1; m1 = l[e]; i1 = e; }
                else if (l[e] > m2) { m2 = l[e]; i2 = e; }
            }
            float r  = expf(m2 - m1);
            float w1 = 1.0f / (1.0f + r);
            float w2 = r * w1;
            te[t * 2 + 0] = i1;  te[t * 2 + 1] = i2;
            tw[t * 2 + 0] = w1;  tw[t * 2 + 1] = w2;
            atomicAdd(&csh[i1], 1);
            atomicAdd(&csh[i2], 1);
        }
        __syncthreads();
        if (tid == 0) {
            int acc = 0;
            for (int e = 0; e < NEXP; e++) {
                g_counts[e] = csh[e];
                g_base[e]   = acc;
                cur[e]      = acc;
                acc += csh[e];
            }
            int nt = 0;
            for (int e = 0; e < NEXP; e++)
                for (int m0 = 0; m0 < csh[e]; m0 += 64) {
                    g_tile_e[nt]  = e;
                    g_tile_m0[nt] = m0;
                    nt++;
                }
            for (; nt < NTILES; nt++) g_tile_e[nt] = -1;
        }
        __syncthreads();
        for (int t = tid; t < T_TOK; t += 256) {
#pragma unroll
            for (int j = 0; j < 2; j++) {
                int e   = te[t * 2 + j];
                int pos = atomicAdd(&cur[e], 1);
                g_slot_tok[pos]         = t;
                g_slot_e[pos]           = e;
                g_slot_w[pos]           = tw[t * 2 + j];
                g_token_slot[t * 2 + j] = pos;
            }
        }
    } else {
        // permutation builder
        const int pb  = blockIdx.x - 1;     // 0..15
        const int mat = pb >> 3;            // 0: w13, 1: w2
        const int e   = pb & 7;
        const int K   = mat ? ID : HD;
        const int G   = mat ? 32 : 8;
        const int KP  = mat ? K2P : K13P;
        const int SC  = mat ? SCHED2 : SCHED13;
        const int* gi = mat ? (gi2 + e * ID) : (gi13 + e * HD);
        int* perm  = mat ? (g_perm2 + e * K2P)   : (g_perm13 + e * K13P);
        int* sched = mat ? (g_sched2 + e * SCHED2) : (g_sched13 + e * SCHED13);

        __shared__ int lh[256 * 32];        // per-thread local hist
        __shared__ int gstart[33];
        const int perth = K / 256;          // 4 or 16
        const int kb = tid * perth;
        for (int g = 0; g < G; g++) lh[tid * G + g] = 0;
        __syncthreads();
        for (int i = 0; i < perth; i++) lh[tid * G + gi[kb + i]]++;
        __syncthreads();
        if (tid == 0) {
            // total counts, padded starts, schedule
            int acc = 0, step = 0;
            for (int g = 0; g < G; g++) {
                int c = 0;
                for (int t = 0; t < 256; t++) c += lh[t * G + g];
                gstart[g] = acc;
                int stp = (c + 15) >> 4;
                for (int s = 0; s < stp; s++)
                    sched[step++] = g | ((s == stp - 1) ? 0x100 : 0);
                acc += stp << 4;
            }
            int nch = (step + 3) >> 2;
            if (mat) g_nch2[e] = nch; else g_nch13[e] = nch;
            for (; step < nch * 4; step++) sched[step] = 0;
            for (; step < SC; step++) sched[step] = 0;
        }
        __syncthreads();
        if (tid < G) {
            int off = gstart[tid];
            for (int t = 0; t < 256; t++) {
                int c = lh[t * G + tid];
                lh[t * G + tid] = off;
                off += c;
            }
        }
        __syncthreads();
        for (int i = tid; i < KP; i += 256) perm[i] = -1;
        __syncthreads();
        for (int i = 0; i < perth; i++) {
            int k = kb + i;
            int g = gi[k];
            perm[lh[tid * G + g]++] = k;
        }
    }
}

// ---------------- prolog: build exact-int bf16 weight matrices -------------
// w13: CTA = (n-tile of 64, e); smem-staged nibble gather along permuted k.
__global__ void k_split_w13(const int* __restrict__ qw) {
    __shared__ int sq[128 * 65];            // [kp][nn], padded stride
    __shared__ int sperm[K13P];
    const int e  = blockIdx.y;
    const int n0 = blockIdx.x * 64;
    const int tid = threadIdx.x;
    for (int i = tid; i < 128 * 64; i += 256) {
        int kp = i >> 6, nn = i & 63;
        sq[kp * 65 + nn] = qw[((size_t)e * 128 + kp) * 8192 + n0 + nn];
    }
    for (int i = tid; i < K13P; i += 256) sperm[i] = g_perm13[e * K13P + i];
    __syncthreads();
    // 64 n x 144 octets; oct fastest -> coalesced 16B stores
    for (int c = tid; c < 64 * (K13P / 8); c += 256) {
        int oct = c % (K13P / 8);
        int nn  = c / (K13P / 8);
        alignas(16) __nv_bfloat16 out[8];
        int4 p0 = *(const int4*)&sperm[oct * 8];
        int4 p1 = *(const int4*)&sperm[oct * 8 + 4];
        int pk[8] = {p0.x, p0.y, p0.z, p0.w, p1.x, p1.y, p1.z, p1.w};
#pragma unroll
        for (int j = 0; j < 8; j++) {
            int k = pk[j];
            int v = (k < 0) ? 0 : (((sq[(k >> 3) * 65 + nn] >> ((k & 7) * 4)) & 15) - 8);
            out[j] = __float2bfloat16((float)v);
        }
        *(uint4*)(g_q13p + ((size_t)e * 8192 + n0 + nn) * K13P + oct * 8) = *(uint4*)out;
    }
}

// w2: CTA = (n-tile of 8, e)
__global__ void k_split_w2(const int* __restrict__ qw) {
    __shared__ int sq[512 * 9];             // [kp][nn], padded
    __shared__ int sperm[K2P];
    const int e  = blockIdx.y;
    const int n0 = blockIdx.x * 8;
    const int tid = threadIdx.x;
    for (int i = tid; i < 512 * 8; i += 256) {
        int kp = i >> 3, nn = i & 7;
        sq[kp * 9 + nn] = qw[((size_t)e * 512 + kp) * 1024 + n0 + nn];
    }
    for (int i = tid; i < K2P; i += 256) sperm[i] = g_perm2[e * K2P + i];
    __syncthreads();
    for (int c = tid; c < 8 * (K2P / 8); c += 256) {
        int oct = c % (K2P / 8);
        int nn  = c / (K2P / 8);
        alignas(16) __nv_bfloat16 out[8];
        int4 p0 = *(const int4*)&sperm[oct * 8];
        int4 p1 = *(const int4*)&sperm[oct * 8 + 4];
        int pk[8] = {p0.x, p0.y, p0.z, p0.w, p1.x, p1.y, p1.z, p1.w};
#pragma unroll
        for (int j = 0; j < 8; j++) {
            int k = pk[j];
            int v = (k < 0) ? 0 : (((sq[(k >> 3) * 9 + nn] >> ((k & 7) * 4)) & 15) - 8);
            out[j] = __float2bfloat16((float)v);
        }
        *(uint4*)(g_q2p + ((size_t)e * 1024 + n0 + nn) * K2P + oct * 8) = *(uint4*)out;
    }
}

// ---------------- prolog: gather x (permuted k), split hi/lo ----------------
__global__ void k_split_x(const float* __restrict__ x) {
    int id  = blockIdx.x * 256 + threadIdx.x;   // slot * 144 + oct
    int oct = id % (K13P / 8);
    int s   = id / (K13P / 8);
    int e   = g_slot_e[s];
    int tok = g_slot_tok[s];
    const int* pm = g_perm13 + e * K13P + oct * 8;
    alignas(16) __nv_bfloat16 h[8], l[8];
#pragma unroll
    for (int j = 0; j < 8; j++) {
        int k = pm[j];
        float v = (k < 0) ? 0.0f : x[(size_t)tok * HD + k];
        split2(v, h[j], l[j]);
    }
    size_t o = (size_t)s * K13P + oct * 8;
    *(uint4*)(g_xah + o) = *(uint4*)h;
    *(uint4*)(g_xal + o) = *(uint4*)l;
}

// ---------------- activation: silu(gate)*up, permuted k2, split hi/lo ------
__global__ void k_act() {
    __shared__ float sa[ID];
    const int s   = blockIdx.x;
    const int tid = threadIdx.x;
    const int e   = g_slot_e[s];
    const float* gp = g_h + (size_t)s * (2 * ID);
    for (int i = tid; i < ID; i += 256) {
        float g = gp[i];
        float u = gp[ID + i];
        sa[i] = g / (1.0f + expf(-g)) * u;
    }
    __syncthreads();
    for (int oct = tid; oct < K2P / 8; oct += 256) {
        const int* pm = g_perm2 + e * K2P + oct * 8;
        alignas(16) __nv_bfloat16 h[8], l[8];
#pragma unroll
        for (int j = 0; j < 8; j++) {
            int k = pm[j];
            float v = (k < 0) ? 0.0f : sa[k];
            split2(v, h[j], l[j]);
        }
        size_t o = (size_t)s * K2P + oct * 8;
        *(uint4*)(g_acth + o) = *(uint4*)h;
        *(uint4*)(g_actl + o) = *(uint4*)l;
    }
}

// ---------------- HMMA 2-term exact-int GEMM -------------------------------
// Block 64x128, BK=64, 256 thr / 8 warps (32x32 warp tiles), 2-stage cp.async,
// 2 CTAs/SM. Terms: xh*q + xl*q into one pacc (q exact int in bf16);
// flush acc += s[g][n]*pacc at group-end steps (sched flags).
#define PITCH_B 144
#define AMAT    (64 * PITCH_B)               // 9216
#define BMAT    (128 * PITCH_B)              // 18432
#define STAGE_BYTES (2 * AMAT + BMAT)        // 36864
#define GTHREADS    256

template<int KP, int G, int NSC, bool G2>
__global__ __launch_bounds__(GTHREADS, 2) void k_gemm(const float* __restrict__ sc) {
    extern __shared__ __align__(128) char smem[];
    const int e = g_tile_e[blockIdx.x];
    if (e < 0) return;
    const int m0   = g_tile_m0[blockIdx.x];
    const int cnt  = g_counts[e];
    const int base = g_base[e];
    const int n0   = blockIdx.y * 128;
    const int tid  = threadIdx.x;
    const int lid  = tid & 31;
    const int wid  = tid >> 5;
    const int wm   = (wid >> 2) * 32;   // warp m offset: 0 / 32
    const int wn   = (wid & 3) * 32;    // warp n offset: 0..96

    const __nv_bfloat16* Axh;
    const __nv_bfloat16* Axl;
    const __nv_bfloat16* Bq;
    const int* schedg;
    int nch;
    if constexpr (G2) {
        Axh = g_acth + (size_t)(base + m0) * KP;
        Axl = g_actl + (size_t)(base + m0) * KP;
        Bq  = g_q2p + (size_t)e * HD * KP + (size_t)n0 * KP;
        schedg = g_sched2 + e * SCHED2;
        nch = g_nch2[e];
    } else {
        Axh = g_xah + (size_t)(base + m0) * KP;
        Axl = g_xal + (size_t)(base + m0) * KP;
        Bq  = g_q13p + (size_t)e * 2 * ID * KP + (size_t)n0 * KP;
        schedg = g_sched13 + e * SCHED13;
        nch = g_nch13[e];
    }

    const uint32_t sbase = smem_u32(smem);
    float* stile = (float*)(smem + 2 * STAGE_BYTES);           // [G][128]
    int*   ssched = (int*)(smem + 2 * STAGE_BYTES + G * 128 * 4);

    // preload scale tile + schedule (plain LDG/STS, covered by first barrier)
    for (int i = tid; i < G * 128; i += GTHREADS) {
        int g = i >> 7, j = i & 127;
        stile[i] = sc[((size_t)e * G + g) * NSC + n0 + j];
    }
    for (int i = tid; i < nch * 4; i += GTHREADS) ssched[i] = schedg[i];

    float acc[2][4][4], pacc[2][4][4];
#pragma unroll
    for (int i = 0; i < 2; i++)
#pragma unroll
        for (int j = 0; j < 4; j++)
#pragma unroll
            for (int k = 0; k < 4; k++) { acc[i][j][k] = 0.0f; pacc[i][j][k] = 0.0f; }

    const uint32_t a_row  = (uint32_t)(lid & 15);
    const uint32_t a_koff = (uint32_t)((lid >> 4) * 16);
    const uint32_t b_row  = (uint32_t)(((lid >> 4) & 1) * 8 + (lid & 7));
    const uint32_t b_koff = (uint32_t)(((lid >> 3) & 1) * 16);
    const int lc = (lid & 3) * 2;

    // stage fill: 2048 16B chunks (A: 2x64x8 = 1024, B: 128x8 = 1024)
    auto issue_stage = [&](uint32_t sb, int k0) {
#pragma unroll
        for (int it = 0; it < 8; it++) {
            int j = it * GTHREADS + tid;
            const __nv_bfloat16* src;
            uint32_t dst;
            if (j < 1024) {
                int mat = j >> 9, jj = j & 511;
                int r = jj >> 3, c = jj & 7;
                src = (mat ? Axl : Axh) + (size_t)r * KP + k0 + c * 8;
                dst = (uint32_t)(mat * AMAT + r * PITCH_B + c * 16);
            } else {
                int jb = j - 1024;
                int r = jb >> 3, c = jb & 7;
                src = Bq + (size_t)r * KP + k0 + c * 8;
                dst = (uint32_t)(2 * AMAT + r * PITCH_B + c * 16);
            }
            cpasync16(sb + dst, src);
        }
        CP_COMMIT();
    };

    issue_stage(sbase, 0);

    for (int ch = 0; ch < nch; ch++) {
        CP_WAIT0();
        __syncthreads();
        const uint32_t buf = sbase + (uint32_t)((ch & 1) * STAGE_BYTES);

        if (ch + 1 < nch)
            issue_stage(sbase + (uint32_t)(((ch + 1) & 1) * STAGE_BYTES),
                        (ch + 1) * 64);

#pragma unroll
        for (int s = 0; s < 4; s++) {
            uint32_t ah[2][4], al[2][4];
#pragma unroll
            for (int mi = 0; mi < 2; mi++) {
                uint32_t ra = buf + (uint32_t)((wm + mi * 16 + a_row) * PITCH_B)
                                  + (uint32_t)(s * 32) + a_koff;
                ldsm4(ah[mi], ra);
                ldsm4(al[mi], ra + AMAT);
            }
            uint32_t bq[2][4];
#pragma unroll
            for (int p = 0; p < 2; p++) {
                uint32_t rb = buf + 2u * AMAT
                                  + (uint32_t)((wn + p * 16 + b_row) * PITCH_B)
                                  + (uint32_t)(s * 32) + b_koff;
                ldsm4(bq[p], rb);
            }
#pragma unroll
            for (int ni = 0; ni < 4; ni++) {
                uint32_t b0 = bq[ni >> 1][(ni & 1) * 2];
                uint32_t b1 = bq[ni >> 1][(ni & 1) * 2 + 1];
#pragma unroll
                for (int mi = 0; mi < 2; mi++) {
                    mma16816(pacc[mi][ni], ah[mi], b0, b1);
                    mma16816(pacc[mi][ni], al[mi], b0, b1);
                }
            }
            // group-boundary flush: acc += s[g][n] * pacc
            int ent = ssched[ch * 4 + s];
            if (ent & 0x100) {
                const float* srow = stile + (ent & 0xFF) * 128;
#pragma unroll
                for (int ni = 0; ni < 4; ni++) {
                    float s0 = srow[wn + ni * 8 + lc];
                    float s1 = srow[wn + ni * 8 + lc + 1];
#pragma unroll
                    for (int mi = 0; mi < 2; mi++) {
                        acc[mi][ni][0] += s0 * pacc[mi][ni][0];
                        acc[mi][ni][1] += s1 * pacc[mi][ni][1];
                        acc[mi][ni][2] += s0 * pacc[mi][ni][2];
                        acc[mi][ni][3] += s1 * pacc[mi][ni][3];
                        pacc[mi][ni][0] = 0.0f; pacc[mi][ni][1] = 0.0f;
                        pacc[mi][ni][2] = 0.0f; pacc[mi][ni][3] = 0.0f;
                    }
                }
            }
        }
    }

    // epilogue: acc (fully scaled) -> global fp32
    const int lr = lid >> 2;
#pragma unroll
    for (int mi = 0; mi < 2; mi++) {
#pragma unroll
        for (int half = 0; half < 2; half++) {
            int row = m0 + wm + mi * 16 + half * 8 + lr;
            if (row < cnt) {
                int gs = base + row;
                if constexpr (!G2) {
                    float* dst = g_h + (size_t)gs * (2 * ID) + n0 + wn + lc;
#pragma unroll
                    for (int ni = 0; ni < 4; ni++) {
                        float2 v = make_float2(acc[mi][ni][half * 2],
                                               acc[mi][ni][half * 2 + 1]);
                        *(float2*)(dst + ni * 8) = v;
                    }
                } else {
                    float w = g_slot_w[gs];
                    float* dst = g_outslot + (size_t)gs * HD + n0 + wn + lc;
#pragma unroll
                    for (int ni = 0; ni < 4; ni++) {
                        float2 v = make_float2(acc[mi][ni][half * 2] * w,
                                               acc[mi][ni][half * 2 + 1] * w);
                        *(float2*)(dst + ni * 8) = v;
                    }
                }
            }
        }
    }
}

#define SMEM1 (2 * STAGE_BYTES + 8 * 128 * 4 + SCHED13 * 4 + 224)   // ~78.3KB
#define SMEM2 (2 * STAGE_BYTES + 32 * 128 * 4 + SCHED2 * 4 + 96)    // ~91.4KB

// ---------------- combine: out[t] = outslot[s0] + outslot[s1] --------------
__global__ void k_combine(float* __restrict__ out) {
    int t = blockIdx.y;
    int n = blockIdx.x * 256 + threadIdx.x;
    int s0 = g_token_slot[t * 2 + 0];
    int s1 = g_token_slot[t * 2 + 1];
    out[(size_t)t * HD + n] = g_outslot[(size_t)s0 * HD + n] +
                              g_outslot[(size_t)s1 * HD + n];
}

// ---------------- launch ----------------------------------------------------
extern "C" void kernel_launch(void* const* d_in, const int* in_sizes, int n_in,
                              void* d_out, int out_size) {
    const float* x      = (const float*)d_in[0];
    const float* logits = (const float*)d_in[1];
    const int*   w13_q  = (const int*)  d_in[2];
    const int*   w2_q   = (const int*)  d_in[3];
    const float* w13_s  = (const float*)d_in[4];
    const float* w2_s   = (const float*)d_in[5];
    const int*   w13_g  = (const int*)  d_in[6];
    const int*   w2_g   = (const int*)  d_in[7];
    float* out = (float*)d_out;
    (void)in_sizes; (void)n_in; (void)out_size;

    static int s_attr_done = 0;
    if (!s_attr_done) {
        cudaFuncSetAttribute(k_gemm<K13P, 8, 8192, false>,
                             cudaFuncAttributeMaxDynamicSharedMemorySize, SMEM1);
        cudaFuncSetAttribute(k_gemm<K2P, 32, 1024, true>,
                             cudaFuncAttributeMaxDynamicSharedMemorySize, SMEM2);
        s_attr_done = 1;
    }

    // launch order: gemm1 is our launch index 3 -> the one ncu captures
    k_route<<<17, 256>>>(logits, w13_g, w2_g);                 // 0
    k_split_w13<<<dim3(128, NEXP), 256>>>(w13_q);              // 1
    k_split_x<<<(NSLOT * (K13P / 8)) / 256, 256>>>(x);         // 2

    // GEMM1: h = x @ q13^T with group-scale flush (y = 64 n-tiles)
    k_gemm<K13P, 8, 8192, false>
        <<<dim3(NTILES, 2 * ID / 128), GTHREADS, SMEM1>>>(w13_s); // 3

    k_split_w2<<<dim3(128, NEXP), 256>>>(w2_q);                // 4
    k_act<<<NSLOT, 256>>>();                                   // 5

    // GEMM2: outslot = act @ q2^T (y = 8 n-tiles)
    k_gemm<K2P, 32, 1024, true>
        <<<dim3(NTILES, HD / 128), GTHREADS, SMEM2>>>(w2_s);   // 6

    k_combine<<<dim3(HD / 256, T_TOK), 256>>>(out);            // 7
}